// round 14
// baseline (speedup 1.0000x reference)
#include <cuda_runtime.h>
#include <cuda_bf16.h>
#include <math.h>
#include <cstdint>

// Problem constants
#define BB   4
#define DIMC 256
#define HH   64
#define WW   64
#define HWSZ 4096
#define NHD  8
#define HDC  32
#define NPP  8
#define NG   (BB * HWSZ)      // 16384 tokens

// ---------------------------------------------------------------------------
// Scratch (device globals: no allocation allowed)
// ---------------------------------------------------------------------------
__device__ __align__(16) unsigned short g_qh[NG * DIMC];   // query bf16 hi, token-major
__device__ __align__(16) unsigned short g_ql[NG * DIMC];   // query bf16 lo
__device__ __align__(16) unsigned short g_vh[NG * DIMC];   // value bf16 hi
__device__ __align__(16) unsigned short g_vl[NG * DIMC];   // value bf16 lo
__device__ __align__(16) unsigned short g_mh[NG * DIMC];   // msda bf16 hi
__device__ __align__(16) unsigned short g_ml[NG * DIMC];   // msda bf16 lo
__device__ __align__(16) unsigned short g_w1h[192 * DIMC]; // [Wloc;Watt] hi
__device__ __align__(16) unsigned short g_w1l[192 * DIMC];
__device__ __align__(16) unsigned short g_w3h[256 * DIMC]; // Wval hi
__device__ __align__(16) unsigned short g_w3l[256 * DIMC];
__device__ __align__(16) unsigned short g_w0h[256 * DIMC]; // Wout hi
__device__ __align__(16) unsigned short g_w0l[256 * DIMC];

__device__ float g_vp [BB * NHD * HWSZ * HDC];   // v_proj, [b][h][yx][d]
__device__ float g_loc[NG * 128];                // loc logits, token-major
__device__ float g_att[NG * 64];                 // att logits, token-major

// ---------------------------------------------------------------------------
// helpers (plain sm_103-compatible: ldmatrix + mma.sync + cp.async)
// ---------------------------------------------------------------------------
__device__ __forceinline__ uint32_t smem_u32(const void* p) {
    uint32_t a;
    asm("{ .reg .u64 t; cvta.to.shared.u64 t, %1; cvt.u32.u64 %0, t; }" : "=r"(a) : "l"(p));
    return a;
}
__device__ __forceinline__ void ldsm_x4(uint32_t (&r)[4], uint32_t addr) {
    asm volatile("ldmatrix.sync.aligned.m8n8.x4.shared.b16 {%0,%1,%2,%3}, [%4];"
        : "=r"(r[0]), "=r"(r[1]), "=r"(r[2]), "=r"(r[3]) : "r"(addr));
}
__device__ __forceinline__ void mma16816(float (&c)[4], const uint32_t (&a)[4],
                                         uint32_t b0, uint32_t b1) {
    asm volatile("mma.sync.aligned.m16n8k16.row.col.f32.bf16.bf16.f32 "
        "{%0,%1,%2,%3}, {%4,%5,%6,%7}, {%8,%9}, {%0,%1,%2,%3};"
        : "+f"(c[0]), "+f"(c[1]), "+f"(c[2]), "+f"(c[3])
        : "r"(a[0]), "r"(a[1]), "r"(a[2]), "r"(a[3]), "r"(b0), "r"(b1));
}
#define CP16(dst_u32, src_ptr) \
    asm volatile("cp.async.cg.shared.global [%0], [%1], 16;" :: "r"(dst_u32), "l"(src_ptr))
#define CP_COMMIT() asm volatile("cp.async.commit_group;" ::: "memory")
#define CP_WAIT0()  asm volatile("cp.async.wait_group 0;" ::: "memory")

__device__ __forceinline__ void pack_hilo4(float4 v, uint2& hi, uint2& lo) {
    __nv_bfloat16 h0 = __float2bfloat16(v.x), h1 = __float2bfloat16(v.y);
    __nv_bfloat16 h2 = __float2bfloat16(v.z), h3 = __float2bfloat16(v.w);
    __nv_bfloat16 l0 = __float2bfloat16(v.x - __bfloat162float(h0));
    __nv_bfloat16 l1 = __float2bfloat16(v.y - __bfloat162float(h1));
    __nv_bfloat16 l2 = __float2bfloat16(v.z - __bfloat162float(h2));
    __nv_bfloat16 l3 = __float2bfloat16(v.w - __bfloat162float(h3));
    hi.x = ((uint32_t)__bfloat16_as_ushort(h1) << 16) | __bfloat16_as_ushort(h0);
    hi.y = ((uint32_t)__bfloat16_as_ushort(h3) << 16) | __bfloat16_as_ushort(h2);
    lo.x = ((uint32_t)__bfloat16_as_ushort(l1) << 16) | __bfloat16_as_ushort(l0);
    lo.y = ((uint32_t)__bfloat16_as_ushort(l3) << 16) | __bfloat16_as_ushort(l2);
}

// ---------------------------------------------------------------------------
// convert_act: transpose query/value [b][k][4096] fp32 -> token-major bf16 hi/lo
// ---------------------------------------------------------------------------
__global__ __launch_bounds__(256)
void convert_act(const float* __restrict__ q, const float* __restrict__ v)
{
    __shared__ float sm[256 * 33];
    const int bi = blockIdx.x;
    const int tensor = bi >> 9;
    const int rem = bi & 511;
    const int b = rem >> 7, tile = rem & 127;
    const float* src = (tensor ? v : q) + (size_t)b * DIMC * HWSZ + tile * 32;

    for (int idx = threadIdx.x; idx < 2048; idx += 256) {
        const int k = idx >> 3, t4 = (idx & 7) * 4;
        const float4 val = *(const float4*)(src + (size_t)k * HWSZ + t4);
        sm[k * 33 + t4 + 0] = val.x;
        sm[k * 33 + t4 + 1] = val.y;
        sm[k * 33 + t4 + 2] = val.z;
        sm[k * 33 + t4 + 3] = val.w;
    }
    __syncthreads();

    unsigned short* dh = tensor ? g_vh : g_qh;
    unsigned short* dl = tensor ? g_vl : g_ql;
    const size_t g0 = (size_t)b * HWSZ + tile * 32;

    for (int idx = threadIdx.x; idx < 1024; idx += 256) {
        const int t = idx >> 5, k8 = (idx & 31) * 8;
        float4 v0, v1;
        v0.x = sm[(k8 + 0) * 33 + t]; v0.y = sm[(k8 + 1) * 33 + t];
        v0.z = sm[(k8 + 2) * 33 + t]; v0.w = sm[(k8 + 3) * 33 + t];
        v1.x = sm[(k8 + 4) * 33 + t]; v1.y = sm[(k8 + 5) * 33 + t];
        v1.z = sm[(k8 + 6) * 33 + t]; v1.w = sm[(k8 + 7) * 33 + t];
        uint2 h0, l0, h1, l1;
        pack_hilo4(v0, h0, l0); pack_hilo4(v1, h1, l1);
        *(uint4*)(dh + (g0 + t) * DIMC + k8) = make_uint4(h0.x, h0.y, h1.x, h1.y);
        *(uint4*)(dl + (g0 + t) * DIMC + k8) = make_uint4(l0.x, l0.y, l1.x, l1.y);
    }
}

// ---------------------------------------------------------------------------
// convert_w: weights fp32 -> bf16 hi/lo planes
// ---------------------------------------------------------------------------
__global__ __launch_bounds__(256)
void convert_w(const float* __restrict__ Wloc, const float* __restrict__ Watt,
               const float* __restrict__ Wval, const float* __restrict__ Wout)
{
    const int idx = blockIdx.x * 256 + threadIdx.x;
    if (idx >= 704 * 32) return;
    const int r = idx >> 5, k8 = (idx & 31) * 8;
    const float* src;
    unsigned short *dh, *dl;
    if (r < 192) {
        src = (r < 128) ? (Wloc + (size_t)r * DIMC) : (Watt + (size_t)(r - 128) * DIMC);
        dh = g_w1h + (size_t)r * DIMC; dl = g_w1l + (size_t)r * DIMC;
    } else if (r < 448) {
        const int rr = r - 192;
        src = Wval + (size_t)rr * DIMC;
        dh = g_w3h + (size_t)rr * DIMC; dl = g_w3l + (size_t)rr * DIMC;
    } else {
        const int rr = r - 448;
        src = Wout + (size_t)rr * DIMC;
        dh = g_w0h + (size_t)rr * DIMC; dl = g_w0l + (size_t)rr * DIMC;
    }
    const float4 v0 = *(const float4*)(src + k8);
    const float4 v1 = *(const float4*)(src + k8 + 4);
    uint2 h0, l0, h1, l1;
    pack_hilo4(v0, h0, l0); pack_hilo4(v1, h1, l1);
    *(uint4*)(dh + k8) = make_uint4(h0.x, h0.y, h1.x, h1.y);
    *(uint4*)(dl + k8) = make_uint4(l0.x, l0.y, l1.x, l1.y);
}

// ---------------------------------------------------------------------------
// bf16-split tensor-core GEMM, small CTAs for 2-4 CTAs/SM co-residency.
// D[m0+0..MT][ny0+0..NT] = A[m][256] . W[n][256]^T + bias
// K chunks of 32, double-buffered cp.async.
// DST: 1 = loc, 2 = att, 3 = vproj, 0 = out
// smem rows are 64B (one K-chunk of a row), swizzle: (ko*16)^(((r>>1)&3)<<4)
// ---------------------------------------------------------------------------
template<int DST, int MT, int NT>
__global__ __launch_bounds__((MT / 64) * (NT / 32) * 32, 512 / ((MT / 64) * (NT / 32) * 32))
void tc_gemm(const float* __restrict__ bias, float* __restrict__ Cout)
{
    constexpr int NW_M = MT / 64;
    constexpr int NW_N = NT / 32;
    constexpr int NTH  = NW_M * NW_N * 32;
    constexpr int BUFB = (MT + NT) * 128;   // Ah|Al|Bh|Bl, one K32 chunk

    extern __shared__ char smraw[];
    const uint32_t sb    = smem_u32(smraw);
    const uint32_t sbase = (sb + 1023) & ~1023u;
    char* smc = smraw + (sbase - sb);

    const int tid  = threadIdx.x;
    const int lane = tid & 31;
    const int wid  = tid >> 5;
    const int wm   = wid % NW_M;
    const int wn   = wid / NW_M;

    const int m0  = blockIdx.x * MT;
    const int ny0 = blockIdx.y * NT;
    const int b   = m0 >> 12;
    const int yx0 = m0 & (HWSZ - 1);

    const char* Ah = (const char*)((DST == 1 || DST == 2) ? g_qh : (DST == 3) ? g_vh : g_mh);
    const char* Al = (const char*)((DST == 1 || DST == 2) ? g_ql : (DST == 3) ? g_vl : g_ml);
    const char* Wh = (const char*)((DST == 1) ? g_w1h : (DST == 2) ? (g_w1h + 128 * DIMC)
                                   : (DST == 3) ? g_w3h : g_w0h);
    const char* Wl = (const char*)((DST == 1) ? g_w1l : (DST == 2) ? (g_w1l + 128 * DIMC)
                                   : (DST == 3) ? g_w3l : g_w0l);

    // ---- async chunk loader (chunk = 32 k = 64 B per row per plane) ----
    auto load_chunk_async = [&](int c) {
        const uint32_t bufb = sbase + (c & 1) * BUFB;
        const int kB = c * 64;
        for (int idx = tid; idx < MT * 4; idx += NTH) {
            const int t = idx >> 2, ko = idx & 3;
            const size_t go = (size_t)(m0 + t) * 512 + kB + ko * 16;
            const uint32_t off = t * 64 + ((ko * 16) ^ (((t >> 1) & 3) << 4));
            CP16(bufb + off, Ah + go);
            CP16(bufb + MT * 64 + off, Al + go);
        }
        for (int idx = tid; idx < NT * 4; idx += NTH) {
            const int n = idx >> 2, ko = idx & 3;
            const size_t go = (size_t)(ny0 + n) * 512 + kB + ko * 16;
            const uint32_t off = n * 64 + ((ko * 16) ^ (((n >> 1) & 3) << 4));
            CP16(bufb + MT * 128 + off, Wh + go);
            CP16(bufb + MT * 128 + NT * 64 + off, Wl + go);
        }
        CP_COMMIT();
    };

    load_chunk_async(0);
    CP_WAIT0();
    __syncthreads();

    float acc[4][4][4];
    #pragma unroll
    for (int i = 0; i < 4; i++)
        #pragma unroll
        for (int j = 0; j < 4; j++)
            #pragma unroll
            for (int q = 0; q < 4; q++) acc[i][j][q] = 0.f;

    const uint32_t khb = (lane >> 4) * 16;    // ldmatrix k-half (bytes)

    for (int c = 0; c < 8; c++) {
        if (c < 7) load_chunk_async(c + 1);   // into other buffer, overlaps mma
        const uint32_t bufb = sbase + (c & 1) * BUFB;
        #pragma unroll
        for (int ks = 0; ks < 2; ks++) {
            const uint32_t kb = ks * 32 + khb;
            uint32_t bh[2][4], bl[2][4];
            #pragma unroll
            for (int np = 0; np < 2; np++) {
                const int nr = wn * 32 + np * 16 + (lane & 15);
                const uint32_t off = nr * 64 + (kb ^ (((nr >> 1) & 3) << 4));
                ldsm_x4(bh[np], bufb + MT * 128 + off);
                ldsm_x4(bl[np], bufb + MT * 128 + NT * 64 + off);
            }
            #pragma unroll
            for (int mt = 0; mt < 4; mt++) {
                const int mr = wm * 64 + mt * 16 + (lane & 15);
                const uint32_t off = mr * 64 + (kb ^ (((mr >> 1) & 3) << 4));
                uint32_t ahf[4], alf[4];
                ldsm_x4(ahf, bufb + off);
                ldsm_x4(alf, bufb + MT * 64 + off);
                #pragma unroll
                for (int nt = 0; nt < 4; nt++) {
                    const int np = nt >> 1, hf = nt & 1;
                    mma16816(acc[mt][nt], ahf, bh[np][hf], bh[np][2 + hf]);
                    mma16816(acc[mt][nt], alf, bh[np][hf], bh[np][2 + hf]);
                    mma16816(acc[mt][nt], ahf, bl[np][hf], bl[np][2 + hf]);
                }
            }
        }
        if (c < 7) {
            CP_WAIT0();
            __syncthreads();
        }
    }
    __syncthreads();

    // ---- epilogue: frags -> smem stage -> (+bias) coalesced global store ----
    constexpr int NTP = NT + 4;
    float* stage = (float*)smc;
    #pragma unroll
    for (int mt = 0; mt < 4; mt++) {
        const int r = wm * 64 + mt * 16 + (lane >> 2);
        #pragma unroll
        for (int nt = 0; nt < 4; nt++) {
            const int cl = wn * 32 + nt * 8 + (lane & 3) * 2;
            stage[r * NTP + cl]           = acc[mt][nt][0];
            stage[r * NTP + cl + 1]       = acc[mt][nt][1];
            stage[(r + 8) * NTP + cl]     = acc[mt][nt][2];
            stage[(r + 8) * NTP + cl + 1] = acc[mt][nt][3];
        }
    }
    __syncthreads();

    for (int idx = tid; idx < MT * (NT / 4); idx += NTH) {
        const int t  = idx / (NT / 4);
        const int nl = (idx % (NT / 4)) * 4;
        const int n  = ny0 + nl;
        float4 v = *(const float4*)(stage + t * NTP + nl);
        const float4 bb4 = *(const float4*)(bias + n);
        v.x += bb4.x; v.y += bb4.y; v.z += bb4.z; v.w += bb4.w;
        if (DST == 3) {
            const int h = n >> 5, d = n & 31;
            *(float4*)(g_vp + ((size_t)((b * NHD + h) * HWSZ) + yx0 + t) * HDC + d) = v;
        } else if (DST == 1) {
            *(float4*)(g_loc + (size_t)(m0 + t) * 128 + n) = v;
        } else if (DST == 2) {
            *(float4*)(g_att + (size_t)(m0 + t) * 64 + n) = v;
        } else {
            *(float4*)(Cout + (size_t)(m0 + t) * 256 + n) = v;
        }
    }
}

// ---------------------------------------------------------------------------
// Sampling, phase-split (unchanged from R13)
// ---------------------------------------------------------------------------
__global__ __launch_bounds__(256)
void sampling_kernel()
{
    extern __shared__ float sms[];
    float4*   swgt4 = (float4*)sms;                    // [8*256]
    float*    smout = sms + 4 * 8 * 256;               // [32][256]
    uint32_t* spak  = (uint32_t*)(smout + 32 * 256);   // [8*256]

    const int tid  = threadIdx.x;
    const int g0   = blockIdx.x * 32;
    const int b    = g0 >> 12;
    const int w    = tid >> 5;
    const int lane = tid & 31;

    // ---- Phase 1: pair = tid (t = tid>>3, h = tid&7) ----
    {
        const int t = tid >> 3, h = tid & 7;
        float e[NPP];
        const float4 a0 = *(const float4*)(g_att + (size_t)(g0 + t) * 64 + h * 8);
        const float4 a1 = *(const float4*)(g_att + (size_t)(g0 + t) * 64 + h * 8 + 4);
        e[0] = a0.x; e[1] = a0.y; e[2] = a0.z; e[3] = a0.w;
        e[4] = a1.x; e[5] = a1.y; e[6] = a1.z; e[7] = a1.w;
        float m = -1e30f;
        #pragma unroll
        for (int p = 0; p < NPP; p++) m = fmaxf(m, e[p]);
        float s = 0.f;
        #pragma unroll
        for (int p = 0; p < NPP; p++) { e[p] = expf(e[p] - m); s += e[p]; }
        const float inv = 1.f / s;

        float L[16];
        #pragma unroll
        for (int q = 0; q < 4; q++)
            *(float4*)(L + q * 4) = *(const float4*)(g_loc + (size_t)(g0 + t) * 128 + h * 16 + q * 4);

        #pragma unroll
        for (int p = 0; p < NPP; p++) {
            const float aw = e[p] * inv;
            const float x = L[2 * p] * (float)WW - 0.5f;
            const float y = L[2 * p + 1] * (float)HH - 0.5f;
            const float xf = floorf(x), yf = floorf(y);
            const float wx = x - xf, wy = y - yf;
            const int x0 = (int)xf, y0 = (int)yf;
            const int x1 = x0 + 1,  y1 = y0 + 1;
            const int x0c = min(max(x0, 0), WW - 1), x1c = min(max(x1, 0), WW - 1);
            const int y0c = min(max(y0, 0), HH - 1), y1c = min(max(y1, 0), HH - 1);
            const bool vx0 = (x0 >= 0) & (x0 < WW);
            const bool vx1 = (x1 >= 0) & (x1 < WW);
            const bool vy0 = (y0 >= 0) & (y0 < HH);
            const bool vy1 = (y1 >= 0) & (y1 < HH);
            float wa = aw * (1.f - wx) * (1.f - wy);
            float wb = aw * wx * (1.f - wy);
            float wc = aw * (1.f - wx) * wy;
            float wd = aw * wx * wy;
            wa = (vx0 && vy0) ? wa : 0.f;
            wb = (vx1 && vy0) ? wb : 0.f;
            wc = (vx0 && vy1) ? wc : 0.f;
            wd = (vx1 && vy1) ? wd : 0.f;
            swgt4[p * 256 + tid] = make_float4(wa, wb, wc, wd);
            spak[p * 256 + tid] = (uint32_t)x0c | ((uint32_t)x1c << 8) |
                                  ((uint32_t)y0c << 16) | ((uint32_t)y1c << 24);
        }
    }
    __syncthreads();

    // ---- Phase 2: gather. warp = 4 pairs x 8 channel-lanes ----
    const int sub = lane >> 3;
    const int d4  = (lane & 7) * 4;

    for (int i = 0; i < 8; i++) {
        const int pid = w * 32 + i * 4 + sub;
        const int tt  = pid >> 3;
        const int h   = pid & 7;
        const float* vpb = g_vp + (size_t)((b * NHD + h) * HWSZ) * HDC + d4;
        float4 acc = make_float4(0.f, 0.f, 0.f, 0.f);
        #pragma unroll
        for (int p = 0; p < NPP; p++) {
            const float4 wv = swgt4[p * 256 + pid];
            const uint32_t pk = spak[p * 256 + pid];
            const int x0c = pk & 255, x1c = (pk >> 8) & 255;
            const int y0r = ((pk >> 16) & 255) << 6;
            const int y1r = (pk >> 24) << 6;
            const float4 v00 = *(const float4*)(vpb + ((y0r + x0c) << 5));
            const float4 v01 = *(const float4*)(vpb + ((y0r + x1c) << 5));
            const float4 v10 = *(const float4*)(vpb + ((y1r + x0c) << 5));
            const float4 v11 = *(const float4*)(vpb + ((y1r + x1c) << 5));
            acc.x += wv.x * v00.x + wv.y * v01.x + wv.z * v10.x + wv.w * v11.x;
            acc.y += wv.x * v00.y + wv.y * v01.y + wv.z * v10.y + wv.w * v11.y;
            acc.z += wv.x * v00.z + wv.y * v01.z + wv.z * v10.z + wv.w * v11.z;
            acc.w += wv.x * v00.w + wv.y * v01.w + wv.z * v10.w + wv.w * v11.w;
        }
        *(float4*)(smout + tt * 256 + h * 32 + d4) = acc;
    }
    __syncthreads();

    // convert + coalesced token-major write of bf16 hi/lo planes
    for (int idx = tid; idx < 32 * 32; idx += 256) {
        const int t = idx >> 5, k8 = (idx & 31) * 8;
        const float4 v0 = *(const float4*)(smout + t * 256 + k8);
        const float4 v1 = *(const float4*)(smout + t * 256 + k8 + 4);
        uint2 h0, l0, h1, l1;
        pack_hilo4(v0, h0, l0); pack_hilo4(v1, h1, l1);
        *(uint4*)(g_mh + (size_t)(g0 + t) * DIMC + k8) = make_uint4(h0.x, h0.y, h1.x, h1.y);
        *(uint4*)(g_ml + (size_t)(g0 + t) * DIMC + k8) = make_uint4(l0.x, l0.y, l1.x, l1.y);
    }
}

// ---------------------------------------------------------------------------
extern "C" void kernel_launch(void* const* d_in, const int* in_sizes, int n_in,
                              void* d_out, int out_size) {
    const float* query = (const float*)d_in[0];
    const float* value = (const float*)d_in[1];
    const float* Wloc  = (const float*)d_in[2];
    const float* bloc  = (const float*)d_in[3];
    const float* Watt  = (const float*)d_in[4];
    const float* batt  = (const float*)d_in[5];
    const float* Wval  = (const float*)d_in[6];
    const float* bval  = (const float*)d_in[7];
    const float* Wout  = (const float*)d_in[8];
    const float* bout  = (const float*)d_in[9];
    float* out = (float*)d_out;

    // smem = max(2*BUFB, MT*(NT+4)*4)
    const int smVP  = 128 * 132 * 4;                    // 67584 (MT=128,NT=128)
    const int smLOC = 2 * (64 + 128) * 128;             // 49152 > 64*132*4=33792
    const int smATT = 2 * (64 + 64) * 128;              // 32768 > 64*68*4=17408
    const int smsamp = (4 * 8 * 256 + 32 * 256) * 4 + 8 * 256 * 4;   // 73728
    cudaFuncSetAttribute(tc_gemm<1, 64, 128>,  cudaFuncAttributeMaxDynamicSharedMemorySize, smLOC);
    cudaFuncSetAttribute(tc_gemm<2, 64, 64>,   cudaFuncAttributeMaxDynamicSharedMemorySize, smATT);
    cudaFuncSetAttribute(tc_gemm<3, 128, 128>, cudaFuncAttributeMaxDynamicSharedMemorySize, smVP);
    cudaFuncSetAttribute(tc_gemm<0, 128, 128>, cudaFuncAttributeMaxDynamicSharedMemorySize, smVP);
    cudaFuncSetAttribute(sampling_kernel, cudaFuncAttributeMaxDynamicSharedMemorySize, smsamp);

    convert_act<<<1024, 256>>>(query, value);
    convert_w<<<88, 256>>>(Wloc, Watt, Wval, Wout);
    tc_gemm<1, 64, 128><<<dim3(256, 1), 128, smLOC>>>(bloc, nullptr);
    tc_gemm<2, 64, 64> <<<dim3(256, 1), 64,  smATT>>>(batt, nullptr);
    tc_gemm<3, 128, 128><<<dim3(128, 2), 256, smVP>>>(bval, nullptr);
    sampling_kernel<<<NG / 32, 256, smsamp>>>();
    tc_gemm<0, 128, 128><<<dim3(128, 2), 256, smVP>>>(bout, out);
}